// round 2
// baseline (speedup 1.0000x reference)
#include <cuda_runtime.h>
#include <cuda_bf16.h>

#define N_ 64
#define T_ 2048
#define D_ 256

// Scratch (no allocs allowed): raw energies + per-row max (ordered-uint encoded)
__device__ float    g_energy[N_ * T_];
__device__ unsigned g_maxbits[N_];

// Order-preserving float->uint encoding (monotone for atomicMax)
__device__ __forceinline__ unsigned fenc(float f) {
    unsigned u = __float_as_uint(f);
    return (u & 0x80000000u) ? ~u : (u | 0x80000000u);
}
__device__ __forceinline__ float fdec(unsigned e) {
    return __uint_as_float((e & 0x80000000u) ? (e ^ 0x80000000u) : ~e);
}

// Robust lens decode: values are in [1, T]. If stored as int64 (little-endian),
// the high word of element 0 (int32 view index 1) is 0; if int32, it's >= 1.
__device__ __forceinline__ int get_len(const int* __restrict__ lens32, int n) {
    const bool is64 = (lens32[1] == 0);
    return is64 ? lens32[2 * n] : lens32[n];
}

// ---------------------------------------------------------------------------
// K0: reset per-row max, zero context output (d_out poisoned to 0xAA)
// ---------------------------------------------------------------------------
__global__ void k_init(float* __restrict__ ctx) {
    int i = blockIdx.x * blockDim.x + threadIdx.x;
    if (i < N_) g_maxbits[i] = 0u;            // below encoding of every finite float
    if (i < N_ * D_) ctx[i] = 0.0f;
}

// ---------------------------------------------------------------------------
// K1: energies e[n,t] = <key[n,t,:], query[n,:]> for t < lens[n]; row max.
// Grid: (T/128, N), 256 threads (8 warps), warp-per-row dot product.
// ---------------------------------------------------------------------------
__global__ void k_energy(const float* __restrict__ q,
                         const float* __restrict__ key,
                         const int* __restrict__ lens32) {
    const int n   = blockIdx.y;
    const int len = get_len(lens32, n);
    const int t0  = blockIdx.x * 128;
    if (t0 >= len) return;                    // skip fully-masked tiles (saves HBM)

    __shared__ float    qs[D_];
    __shared__ unsigned bmax;
    const int tid = threadIdx.x;
    if (tid == 0) bmax = 0u;
    qs[tid] = q[n * D_ + tid];
    __syncthreads();

    const int warp = tid >> 5, lane = tid & 31;
    const float4 qa = *(const float4*)&qs[lane * 8];
    const float4 qb = *(const float4*)&qs[lane * 8 + 4];

    unsigned lmax = 0u;
    #pragma unroll
    for (int it = 0; it < 16; ++it) {
        const int t = t0 + it * 8 + warp;     // warp-uniform
        if (t >= len) continue;
        const float* krow = key + ((size_t)n * T_ + t) * D_;
        const float4 ka = *(const float4*)&krow[lane * 8];
        const float4 kb = *(const float4*)&krow[lane * 8 + 4];
        float s = ka.x * qa.x + ka.y * qa.y + ka.z * qa.z + ka.w * qa.w
                + kb.x * qb.x + kb.y * qb.y + kb.z * qb.z + kb.w * qb.w;
        #pragma unroll
        for (int o = 16; o; o >>= 1) s += __shfl_xor_sync(0xffffffff, s, o);
        if (lane == 0) {
            g_energy[n * T_ + t] = s;
            unsigned e = fenc(s);
            if (e > lmax) lmax = e;
        }
    }
    if (lane == 0 && lmax) atomicMax(&bmax, lmax);
    __syncthreads();
    if (tid == 0 && bmax) atomicMax(&g_maxbits[n], bmax);
}

// ---------------------------------------------------------------------------
// K2: per-row softmax over valid prefix; write normalized attention (0 in tail)
// Grid: N CTAs x 256 threads. Touches only the 512KB energy scratch (L2-hot).
// ---------------------------------------------------------------------------
__global__ void k_softmax(const int* __restrict__ lens32,
                          float* __restrict__ attn) {
    const int n   = blockIdx.x;
    const int len = get_len(lens32, n);
    const float m = fdec(g_maxbits[n]);
    const int tid = threadIdx.x;

    float s = 0.0f;
    for (int t = tid; t < len; t += 256)
        s += __expf(g_energy[n * T_ + t] - m);

    __shared__ float red[256];
    red[tid] = s;
    __syncthreads();
    #pragma unroll
    for (int o = 128; o; o >>= 1) {
        if (tid < o) red[tid] += red[tid + o];
        __syncthreads();
    }
    const float invZ = 1.0f / red[0];

    for (int t = tid; t < T_; t += 256)
        attn[n * T_ + t] = (t < len) ? __expf(g_energy[n * T_ + t] - m) * invZ : 0.0f;
}

// ---------------------------------------------------------------------------
// K3: context[n,d] = sum_t p[n,t] * value[n,t,d], split over t-tiles,
// partial sums merged with atomicAdd. Thread d owns column d (coalesced V).
// Grid: (T/256, N) x 256 threads.
// ---------------------------------------------------------------------------
__global__ void k_context(const float* __restrict__ val,
                          const int* __restrict__ lens32,
                          const float* __restrict__ attn,
                          float* __restrict__ ctx) {
    const int n   = blockIdx.y;
    const int len = get_len(lens32, n);
    const int t0  = blockIdx.x * 256;
    if (t0 >= len) return;
    const int cnt = min(256, len - t0);
    const int d   = threadIdx.x;

    __shared__ float ps[256];
    ps[d] = (d < cnt) ? attn[n * T_ + t0 + d] : 0.0f;
    __syncthreads();

    const float* vbase = val + ((size_t)n * T_ + t0) * D_ + d;
    float acc = 0.0f;
    #pragma unroll 8
    for (int i = 0; i < cnt; ++i)
        acc += ps[i] * vbase[(size_t)i * D_];

    atomicAdd(&ctx[n * D_ + d], acc);
}

// ---------------------------------------------------------------------------
extern "C" void kernel_launch(void* const* d_in, const int* in_sizes, int n_in,
                              void* d_out, int out_size) {
    const float* q    = (const float*)d_in[0];
    const float* key  = (const float*)d_in[1];
    const float* val  = (const float*)d_in[2];
    const int*   lens = (const int*)d_in[3];
    float* ctx  = (float*)d_out;            // first tuple element: [N, D]
    float* attn = (float*)d_out + N_ * D_;  // second tuple element: [N, T]

    k_init<<<(N_ * D_ + 255) / 256, 256>>>(ctx);
    k_energy<<<dim3(T_ / 128, N_), 256>>>(q, key, lens);
    k_softmax<<<N_, 256>>>(lens, attn);
    k_context<<<dim3(T_ / 256, N_), 256>>>(val, lens, attn, ctx);
}

// round 3
// speedup vs baseline: 1.3490x; 1.3490x over previous
#include <cuda_runtime.h>
#include <cuda_bf16.h>

#define N_ 64
#define T_ 2048
#define D_ 256

// Scratch (no allocs allowed): raw energies + per-row max (ordered-uint encoded)
__device__ float    g_energy[N_ * T_];
__device__ unsigned g_maxbits[N_];

// Order-preserving float->uint encoding (monotone for atomicMax)
__device__ __forceinline__ unsigned fenc(float f) {
    unsigned u = __float_as_uint(f);
    return (u & 0x80000000u) ? ~u : (u | 0x80000000u);
}
__device__ __forceinline__ float fdec(unsigned e) {
    return __uint_as_float((e & 0x80000000u) ? (e ^ 0x80000000u) : ~e);
}

// Robust lens decode: values are in [1, T]. If stored as int64 (little-endian),
// the high word of element 0 (int32 view index 1) is 0; if int32, it's >= 1.
__device__ __forceinline__ int get_len(const int* __restrict__ lens32, int n) {
    const bool is64 = (lens32[1] == 0);
    return is64 ? lens32[2 * n] : lens32[n];
}

// ---------------------------------------------------------------------------
// K0: reset per-row max, zero context output (d_out poisoned to 0xAA)
// ---------------------------------------------------------------------------
__global__ void k_init(float* __restrict__ ctx) {
    int i = blockIdx.x * blockDim.x + threadIdx.x;
    if (i < N_) g_maxbits[i] = 0u;            // below encoding of every finite float
    if (i < N_ * D_) ctx[i] = 0.0f;
}

// ---------------------------------------------------------------------------
// K1: energies e[n,t] = <key[n,t,:], query[n,:]> for t < lens[n]; row max.
// Grid: (T/64, N), 256 threads. 8 lanes per row => each lane does 8 unrolled
// float4 loads (32 independent loads in flight per warp), 3-level shfl reduce.
// ---------------------------------------------------------------------------
__global__ void k_energy(const float* __restrict__ q,
                         const float* __restrict__ key,
                         const int* __restrict__ lens32) {
    const int n   = blockIdx.y;
    const int len = get_len(lens32, n);
    const int t0  = blockIdx.x * 64;
    if (t0 >= len) return;                    // skip fully-masked tiles (saves HBM)

    __shared__ float4   qs4[D_ / 4];
    __shared__ unsigned bmax;
    const int tid = threadIdx.x;
    if (tid == 0) bmax = 0u;
    if (tid < 64) qs4[tid] = ((const float4*)(q + n * D_))[tid];
    __syncthreads();

    const int warp = tid >> 5, lane = tid & 31;
    const int sub  = lane >> 3;               // row within 4-row group
    const int sl   = lane & 7;                // lane within row (8 lanes/row)

    unsigned lmax = 0u;
    #pragma unroll
    for (int iter = 0; iter < 2; ++iter) {
        const int t = t0 + warp * 8 + iter * 4 + sub;
        float s = 0.0f;
        if (t < len) {
            const float4* krow = (const float4*)(key + ((size_t)n * T_ + t) * D_);
            #pragma unroll
            for (int k = 0; k < 8; ++k) {     // 8 independent 16B loads in flight
                const float4 kv = krow[sl + k * 8];
                const float4 qv = qs4[sl + k * 8];
                s += kv.x * qv.x + kv.y * qv.y + kv.z * qv.z + kv.w * qv.w;
            }
        }
        // reduce across the 8 lanes of this row (all lanes execute: no divergence)
        s += __shfl_xor_sync(0xffffffff, s, 4);
        s += __shfl_xor_sync(0xffffffff, s, 2);
        s += __shfl_xor_sync(0xffffffff, s, 1);
        if (sl == 0 && t < len) {
            g_energy[n * T_ + t] = s;
            const unsigned e = fenc(s);
            if (e > lmax) lmax = e;
        }
    }
    if (lmax) atomicMax(&bmax, lmax);
    __syncthreads();
    if (tid == 0 && bmax) atomicMax(&g_maxbits[n], bmax);
}

// ---------------------------------------------------------------------------
// K2: per-row softmax over valid prefix; write normalized attention (0 in tail)
// Grid: N CTAs x 256 threads. Touches only the 512KB energy scratch (L2-hot).
// ---------------------------------------------------------------------------
__global__ void k_softmax(const int* __restrict__ lens32,
                          float* __restrict__ attn) {
    const int n   = blockIdx.x;
    const int len = get_len(lens32, n);
    const float m = fdec(g_maxbits[n]);
    const int tid = threadIdx.x;

    float s = 0.0f;
    for (int t = tid; t < len; t += 256)
        s += __expf(g_energy[n * T_ + t] - m);

    __shared__ float red[256];
    red[tid] = s;
    __syncthreads();
    #pragma unroll
    for (int o = 128; o; o >>= 1) {
        if (tid < o) red[tid] += red[tid + o];
        __syncthreads();
    }
    const float invZ = 1.0f / red[0];

    for (int t = tid; t < T_; t += 256)
        attn[n * T_ + t] = (t < len) ? __expf(g_energy[n * T_ + t] - m) * invZ : 0.0f;
}

// ---------------------------------------------------------------------------
// K3: context[n,d] = sum_t p[n,t] * value[n,t,d]. Tile = 128 t-rows.
// Thread owns float4 column d4 (16B), 4 row-groups in parallel; unroll-4 gives
// 4 independent 16B loads in flight per thread. Partial sums -> smem -> atomicAdd.
// Grid: (T/128, N) x 256 threads.
// ---------------------------------------------------------------------------
__global__ void k_context(const float* __restrict__ val,
                          const int* __restrict__ lens32,
                          const float* __restrict__ attn,
                          float* __restrict__ ctx) {
    const int n   = blockIdx.y;
    const int len = get_len(lens32, n);
    const int t0  = blockIdx.x * 128;
    if (t0 >= len) return;
    const int cnt = min(128, len - t0);
    const int tid = threadIdx.x;
    const int d4  = tid & 63;                 // float4 column index (64 * 16B = 1KB row)
    const int rg  = tid >> 6;                 // row group 0..3

    __shared__ float  ps[128];
    __shared__ float4 red[4][64];
    if (tid < 128) ps[tid] = (tid < cnt) ? attn[n * T_ + t0 + tid] : 0.0f;
    __syncthreads();

    const float4* v4 = (const float4*)(val + ((size_t)n * T_ + t0) * D_) + d4;
    float4 acc = make_float4(0.f, 0.f, 0.f, 0.f);
    #pragma unroll 4
    for (int i = rg; i < cnt; i += 4) {       // independent loads across unrolled iters
        const float  p = ps[i];
        const float4 v = v4[(size_t)i * 64];
        acc.x += p * v.x; acc.y += p * v.y; acc.z += p * v.z; acc.w += p * v.w;
    }

    red[rg][d4] = acc;
    __syncthreads();
    if (rg == 0) {
        const float4 a = red[0][d4], b = red[1][d4], c = red[2][d4], e = red[3][d4];
        float* dst = &ctx[n * D_ + d4 * 4];
        atomicAdd(dst + 0, a.x + b.x + c.x + e.x);
        atomicAdd(dst + 1, a.y + b.y + c.y + e.y);
        atomicAdd(dst + 2, a.z + b.z + c.z + e.z);
        atomicAdd(dst + 3, a.w + b.w + c.w + e.w);
    }
}

// ---------------------------------------------------------------------------
extern "C" void kernel_launch(void* const* d_in, const int* in_sizes, int n_in,
                              void* d_out, int out_size) {
    const float* q    = (const float*)d_in[0];
    const float* key  = (const float*)d_in[1];
    const float* val  = (const float*)d_in[2];
    const int*   lens = (const int*)d_in[3];
    float* ctx  = (float*)d_out;            // first tuple element: [N, D]
    float* attn = (float*)d_out + N_ * D_;  // second tuple element: [N, T]

    k_init<<<(N_ * D_ + 255) / 256, 256>>>(ctx);
    k_energy<<<dim3(T_ / 64, N_), 256>>>(q, key, lens);
    k_softmax<<<N_, 256>>>(lens, attn);
    k_context<<<dim3(T_ / 128, N_), 256>>>(val, lens, attn, ctx);
}